// round 11
// baseline (speedup 1.0000x reference)
#include <cuda_runtime.h>
#include <cuda_fp16.h>
#include <cstdint>

// Sparse embedding-bag: out[b,:] = bias + sum_k weight[ft_ics[b,k],:] * ft_vals[b,k]
// B=16384, K=32, N_OUT=256. Table 41024x256 fp32 = 42 MB.
//
// R11 (= R8 winner + balanced convert wave):
//  - Gather: fp16 table, warp=row, 4 coalesced LDG.32/feature, KU=8 (32 loads
//    in flight). Pinned at the LTS random-line cap (~22.6us) across 6 variants.
//  - Convert: grid-stride float4 body (measured best at 4.5us); grid = 1184
//    blocks = 148 SMs x 8 resident -> exactly one balanced wave (no wave
//    transitions, no tail). One-shot flat grids cost +2.2us (R9/R10 evidence).

#define N_IN_ROWS 41024
#define N_OUT_COLS 256
#define K_FEATS 32
#define ROWS_PER_BLOCK 8
#define KU 8

__device__ __half g_w16[(size_t)N_IN_ROWS * N_OUT_COLS];

// ---------------- conversion: fp32 table -> fp16 table (streaming) ----------
__global__ __launch_bounds__(256)
void convert_w16_kernel(const float4* __restrict__ w32)
{
    const size_t n4 = (size_t)N_IN_ROWS * N_OUT_COLS / 4;
    uint2* dst = reinterpret_cast<uint2*>(g_w16);
    for (size_t i = (size_t)blockIdx.x * blockDim.x + threadIdx.x;
         i < n4; i += (size_t)gridDim.x * blockDim.x) {
        const float4 w = __ldg(&w32[i]);
        __half2 h0 = __floats2half2_rn(w.x, w.y);
        __half2 h1 = __floats2half2_rn(w.z, w.w);
        uint2 u;
        u.x = *reinterpret_cast<unsigned*>(&h0);
        u.y = *reinterpret_cast<unsigned*>(&h1);
        dst[i] = u;   // write-back: fp16 table stays L2-resident for the gather
    }
}

// ---------------- gather: fp16 table, fp32 accumulate -----------------------
// Warp = one batch row. Lane tx owns column pairs {c*64+2tx, +1 : c=0..3}.
// Each feature row = 128 half2; warp covers it with 4 coalesced LDG.32
// (one 128B line each). KU=8 features front-batched -> 32 loads in flight.
__global__ __launch_bounds__(32 * ROWS_PER_BLOCK, 4)
void ft_embed_bag_kernel(const int* __restrict__ ics,
                         const float* __restrict__ vals,
                         const float* __restrict__ bias,   // [256]
                         float* __restrict__ out)          // [B][256]
{
    __shared__ int   s_idx[ROWS_PER_BLOCK][K_FEATS];
    __shared__ float s_val[ROWS_PER_BLOCK][K_FEATS];

    const int ty = threadIdx.y;
    const int tx = threadIdx.x;
    const int b  = blockIdx.x * ROWS_PER_BLOCK + ty;

    {
        const int   raw = __ldg(&ics[b * K_FEATS + tx]);
        const float v   = __ldg(&vals[b * K_FEATS + tx]);
        const bool valid = (raw >= 0);
        s_idx[ty][tx] = valid ? raw : 0;
        s_val[ty][tx] = valid ? v : 0.0f;
    }
    __syncwarp();

    // acc[2c], acc[2c+1] = output cols c*64 + 2tx, c*64 + 2tx + 1
    float acc[8];
    #pragma unroll
    for (int c = 0; c < 4; ++c) {
        acc[2 * c]     = __ldg(&bias[c * 64 + 2 * tx]);
        acc[2 * c + 1] = __ldg(&bias[c * 64 + 2 * tx + 1]);
    }

    const __half2* wtab = reinterpret_cast<const __half2*>(g_w16);

    #pragma unroll
    for (int k0 = 0; k0 < K_FEATS; k0 += KU) {
        int   idx[KU];
        float v[KU];
        #pragma unroll
        for (int j = 0; j < KU; ++j) {
            idx[j] = s_idx[ty][k0 + j];
            v[j]   = s_val[ty][k0 + j];
        }

        // Front-batch 4*KU = 32 independent coalesced LDG.32 (one line each).
        __half2 w[KU][4];
        #pragma unroll
        for (int j = 0; j < KU; ++j) {
            const __half2* base = wtab + (size_t)idx[j] * 128 + tx;
            #pragma unroll
            for (int c = 0; c < 4; ++c)
                w[j][c] = __ldg(base + c * 32);
        }

        #pragma unroll
        for (int j = 0; j < KU; ++j) {
            #pragma unroll
            for (int c = 0; c < 4; ++c) {
                const float2 wf = __half22float2(w[j][c]);
                acc[2 * c]     = fmaf(v[j], wf.x, acc[2 * c]);
                acc[2 * c + 1] = fmaf(v[j], wf.y, acc[2 * c + 1]);
            }
        }
    }

    // Streaming float2 stores (single-use output).
    float* orow = out + (size_t)b * N_OUT_COLS;
    #pragma unroll
    for (int c = 0; c < 4; ++c) {
        float2 o = make_float2(acc[2 * c], acc[2 * c + 1]);
        __stcs(reinterpret_cast<float2*>(orow + c * 64) + tx, o);
    }
}

extern "C" void kernel_launch(void* const* d_in, const int* in_sizes, int n_in,
                              void* d_out, int out_size)
{
    const int*   ics    = (const int*)d_in[0];
    const float* vals   = (const float*)d_in[1];
    const float* weight = (const float*)d_in[2];
    const float* bias   = (const float*)d_in[3];
    float*       out    = (float*)d_out;

    const int B = in_sizes[0] / K_FEATS;  // 16384

    // One balanced wave: 148 SMs x 8 resident blocks.
    convert_w16_kernel<<<1184, 256>>>((const float4*)weight);

    dim3 block(32, ROWS_PER_BLOCK);
    dim3 grid(B / ROWS_PER_BLOCK);
    ft_embed_bag_kernel<<<grid, block>>>(ics, vals, bias, out);
}

// round 12
// speedup vs baseline: 1.5016x; 1.5016x over previous
#include <cuda_runtime.h>
#include <cuda_fp16.h>
#include <cstdint>

// Sparse embedding-bag: out[b,:] = bias + sum_k weight[ft_ics[b,k],:] * ft_vals[b,k]
// B=16384, K=32, N_OUT=256. Table 41024x256 fp32 = 42 MB.
//
// R12 = R8 verbatim (best measured: 27.1us total; gather 22.6us = LTS
// random-line cap, convert 4.5us = streaming floor). R11's 43.8us with a
// byte-identical gather kernel was environmental (uniform 1.49x slowdown,
// HBM 1115->747 GB/s at fixed bytes) -- re-benching the proven config to
// re-validate the floor before any further change.

#define N_IN_ROWS 41024
#define N_OUT_COLS 256
#define K_FEATS 32
#define ROWS_PER_BLOCK 8
#define KU 8

__device__ __half g_w16[(size_t)N_IN_ROWS * N_OUT_COLS];

// ---------------- conversion: fp32 table -> fp16 table (streaming) ----------
__global__ __launch_bounds__(256)
void convert_w16_kernel(const float4* __restrict__ w32)
{
    const size_t n4 = (size_t)N_IN_ROWS * N_OUT_COLS / 4;
    uint2* dst = reinterpret_cast<uint2*>(g_w16);
    for (size_t i = (size_t)blockIdx.x * blockDim.x + threadIdx.x;
         i < n4; i += (size_t)gridDim.x * blockDim.x) {
        const float4 w = __ldg(&w32[i]);
        __half2 h0 = __floats2half2_rn(w.x, w.y);
        __half2 h1 = __floats2half2_rn(w.z, w.w);
        uint2 u;
        u.x = *reinterpret_cast<unsigned*>(&h0);
        u.y = *reinterpret_cast<unsigned*>(&h1);
        dst[i] = u;   // write-back: fp16 table stays L2-resident for the gather
    }
}

// ---------------- gather: fp16 table, fp32 accumulate -----------------------
// Warp = one batch row. Lane tx owns column pairs {c*64+2tx, +1 : c=0..3}.
// Each feature row = 128 half2; warp covers it with 4 coalesced LDG.32
// (one 128B line each). KU=8 features front-batched -> 32 loads in flight.
__global__ __launch_bounds__(32 * ROWS_PER_BLOCK, 4)
void ft_embed_bag_kernel(const int* __restrict__ ics,
                         const float* __restrict__ vals,
                         const float* __restrict__ bias,   // [256]
                         float* __restrict__ out)          // [B][256]
{
    __shared__ int   s_idx[ROWS_PER_BLOCK][K_FEATS];
    __shared__ float s_val[ROWS_PER_BLOCK][K_FEATS];

    const int ty = threadIdx.y;
    const int tx = threadIdx.x;
    const int b  = blockIdx.x * ROWS_PER_BLOCK + ty;

    {
        const int   raw = __ldg(&ics[b * K_FEATS + tx]);
        const float v   = __ldg(&vals[b * K_FEATS + tx]);
        const bool valid = (raw >= 0);
        s_idx[ty][tx] = valid ? raw : 0;
        s_val[ty][tx] = valid ? v : 0.0f;
    }
    __syncwarp();

    // acc[2c], acc[2c+1] = output cols c*64 + 2tx, c*64 + 2tx + 1
    float acc[8];
    #pragma unroll
    for (int c = 0; c < 4; ++c) {
        acc[2 * c]     = __ldg(&bias[c * 64 + 2 * tx]);
        acc[2 * c + 1] = __ldg(&bias[c * 64 + 2 * tx + 1]);
    }

    const __half2* wtab = reinterpret_cast<const __half2*>(g_w16);

    #pragma unroll
    for (int k0 = 0; k0 < K_FEATS; k0 += KU) {
        int   idx[KU];
        float v[KU];
        #pragma unroll
        for (int j = 0; j < KU; ++j) {
            idx[j] = s_idx[ty][k0 + j];
            v[j]   = s_val[ty][k0 + j];
        }

        // Front-batch 4*KU = 32 independent coalesced LDG.32 (one line each).
        __half2 w[KU][4];
        #pragma unroll
        for (int j = 0; j < KU; ++j) {
            const __half2* base = wtab + (size_t)idx[j] * 128 + tx;
            #pragma unroll
            for (int c = 0; c < 4; ++c)
                w[j][c] = __ldg(base + c * 32);
        }

        #pragma unroll
        for (int j = 0; j < KU; ++j) {
            #pragma unroll
            for (int c = 0; c < 4; ++c) {
                const float2 wf = __half22float2(w[j][c]);
                acc[2 * c]     = fmaf(v[j], wf.x, acc[2 * c]);
                acc[2 * c + 1] = fmaf(v[j], wf.y, acc[2 * c + 1]);
            }
        }
    }

    // Streaming float2 stores (single-use output).
    float* orow = out + (size_t)b * N_OUT_COLS;
    #pragma unroll
    for (int c = 0; c < 4; ++c) {
        float2 o = make_float2(acc[2 * c], acc[2 * c + 1]);
        __stcs(reinterpret_cast<float2*>(orow + c * 64) + tx, o);
    }
}

extern "C" void kernel_launch(void* const* d_in, const int* in_sizes, int n_in,
                              void* d_out, int out_size)
{
    const int*   ics    = (const int*)d_in[0];
    const float* vals   = (const float*)d_in[1];
    const float* weight = (const float*)d_in[2];
    const float* bias   = (const float*)d_in[3];
    float*       out    = (float*)d_out;

    const int B = in_sizes[0] / K_FEATS;  // 16384

    convert_w16_kernel<<<2048, 256>>>((const float4*)weight);

    dim3 block(32, ROWS_PER_BLOCK);
    dim3 grid(B / ROWS_PER_BLOCK);
    ft_embed_bag_kernel<<<grid, block>>>(ics, vals, bias, out);
}